// round 1
// baseline (speedup 1.0000x reference)
#include <cuda_runtime.h>
#include <cuda_bf16.h>
#include <cstdint>

// ---------------------------------------------------------------------------
// SMPL joint regression:
//   out[b,j,:] = FK(rodrigues(pose[b]), J[b])[:, :3, 3] + trans[b]
//   J[b] = J_regressor @ (v_template + shapedirs . betas[b])
// Key decomposition: contract the 6890-vertex dimension ONCE (batch-indep):
//   Jbase[j,k]    = sum_i Jreg[j,i] * vt[i,k]
//   JS[j,k,l]     = sum_i Jreg[j,i] * sd[i,k,l]
// then per batch J = Jbase + JS . beta  (720 FFMA).
// ---------------------------------------------------------------------------

#define NUM_VERTS 6890
#define VB 128
#define NBLK_A 54            // ceil(6890/128)
#define NBASIS 792           // 24 joints * 33 cols (3 vt + 30 sd)

__device__ float g_part[NBLK_A][NBASIS];
__device__ float g_final[NBASIS];   // [0..71]=Jbase(j*3+k), [72+l*72+j*3+k]=JS

// ---------------- Kernel A: per-chunk partial basis --------------------------
__global__ void __launch_bounds__(256) kA(const float* __restrict__ vt,
                                          const float* __restrict__ sd,
                                          const float* __restrict__ jr) {
    __shared__ float Xs[VB][33];      // col 0..2 = v_template, 3..32 = shapedirs
    __shared__ float Jr[24][VB];
    const int i0 = blockIdx.x * VB;
    const int tid = threadIdx.x;

    for (int idx = tid; idx < VB * 30; idx += 256) {
        int i = idx / 30, c = idx % 30;
        float v = 0.f;
        if (i0 + i < NUM_VERTS) v = sd[(size_t)i0 * 30 + idx];
        Xs[i][3 + c] = v;
    }
    for (int idx = tid; idx < VB * 3; idx += 256) {
        int i = idx / 3, k = idx % 3;
        float v = 0.f;
        if (i0 + i < NUM_VERTS) v = vt[(size_t)(i0 + i) * 3 + k];
        Xs[i][k] = v;
    }
    for (int idx = tid; idx < 24 * VB; idx += 256) {
        int j = idx >> 7, i = idx & (VB - 1);
        float v = 0.f;
        if (i0 + i < NUM_VERTS) v = jr[j * NUM_VERTS + i0 + i];
        Jr[j][i] = v;
    }
    __syncthreads();

    const int w = tid >> 5, l = tid & 31;
    const int j0 = w, j1 = w + 8, j2 = w + 16;
    float a0 = 0.f, a1 = 0.f, a2 = 0.f;   // column l
    float b0 = 0.f, b1 = 0.f, b2 = 0.f;   // column 32 (broadcast, lane 0 keeps)
#pragma unroll 8
    for (int i = 0; i < VB; i++) {
        float r0 = Jr[j0][i], r1 = Jr[j1][i], r2 = Jr[j2][i];
        float x  = Xs[i][l];
        float xb = Xs[i][32];
        a0 += r0 * x;  a1 += r1 * x;  a2 += r2 * x;
        b0 += r0 * xb; b1 += r1 * xb; b2 += r2 * xb;
    }
    float* P = g_part[blockIdx.x];
    P[j0 * 33 + l] = a0;
    P[j1 * 33 + l] = a1;
    P[j2 * 33 + l] = a2;
    if (l == 0) {
        P[j0 * 33 + 32] = b0;
        P[j1 * 33 + 32] = b1;
        P[j2 * 33 + 32] = b2;
    }
}

// ---------------- Kernel A2: reduce partials + remap -------------------------
__global__ void kA2() {
    int o = blockIdx.x * blockDim.x + threadIdx.x;
    if (o >= NBASIS) return;
    float s = 0.f;
#pragma unroll
    for (int p = 0; p < NBLK_A; p++) s += g_part[p][o];
    int j = o / 33, c = o % 33;
    int v;
    if (c < 3) v = j * 3 + c;
    else {
        int k = (c - 3) / 10, l = (c - 3) % 10;
        v = 72 + l * 72 + j * 3 + k;
    }
    g_final[v] = s;
}

// ---------------- Kernel B: per-batch Rodrigues + FK -------------------------
__global__ void __launch_bounds__(128) kB(const float* __restrict__ pose,
                                          const float* __restrict__ trans,
                                          const float* __restrict__ betas,
                                          float* __restrict__ out) {
    __shared__ float Jb[NBASIS];
    __shared__ float Ps[128][73];   // pose staging, padded (73 odd -> no conflicts)
    __shared__ float Bs[128][11];
    __shared__ float Ts[128][3];
    const int tid = threadIdx.x;
    const int b0 = blockIdx.x * 128;

    for (int v = tid; v < NBASIS; v += 128) Jb[v] = g_final[v];
    {
        const float* psrc = pose + (size_t)b0 * 72;
        for (int idx = tid; idx < 128 * 72; idx += 128) Ps[idx / 72][idx % 72] = psrc[idx];
        const float* bsrc = betas + (size_t)b0 * 10;
        for (int idx = tid; idx < 128 * 10; idx += 128) Bs[idx / 10][idx % 10] = bsrc[idx];
        const float* tsrc = trans + (size_t)b0 * 3;
        for (int idx = tid; idx < 128 * 3; idx += 128) Ts[idx / 3][idx % 3] = tsrc[idx];
    }
    __syncthreads();

    // J = Jbase + JS . beta
    float bet[10];
#pragma unroll
    for (int l = 0; l < 10; l++) bet[l] = Bs[tid][l];
    float J[72];
#pragma unroll
    for (int v = 0; v < 72; v++) J[v] = Jb[v];
#pragma unroll
    for (int l = 0; l < 10; l++) {
#pragma unroll
        for (int v = 0; v < 72; v++) J[v] += bet[l] * Jb[72 + l * 72 + v];
    }
    const float tx = Ts[tid][0], ty = Ts[tid][1], tz = Ts[tid][2];

    const int PAR[24] = {-1, 0, 0, 0, 1, 2, 3, 4, 5, 6, 7, 8,
                          9, 9, 9, 12, 13, 14, 16, 17, 18, 19, 20, 21};

    float cR[24][9], cT[24][3];
#pragma unroll
    for (int j = 0; j < 24; j++) {
        // --- Rodrigues (matches reference: angle = ||v + eps|| per-component) ---
        float vx = Ps[tid][3 * j + 0];
        float vy = Ps[tid][3 * j + 1];
        float vz = Ps[tid][3 * j + 2];
        float ax = vx + 1e-8f, ay = vy + 1e-8f, az = vz + 1e-8f;
        float n2 = ax * ax + ay * ay + az * az;
        float inv = rsqrtf(n2);
        float ang = n2 * inv;
        float x = vx * inv, y = vy * inv, z = vz * inv;
        float s, c;
        __sincosf(ang, &s, &c);
        float t1 = 1.f - c;
        float R[9];
        R[0] = 1.f - t1 * (y * y + z * z);
        R[1] = -s * z + t1 * x * y;
        R[2] =  s * y + t1 * x * z;
        R[3] =  s * z + t1 * x * y;
        R[4] = 1.f - t1 * (x * x + z * z);
        R[5] = -s * x + t1 * y * z;
        R[6] = -s * y + t1 * x * z;
        R[7] =  s * x + t1 * y * z;
        R[8] = 1.f - t1 * (x * x + y * y);

        int p = PAR[j];
        float rx, ry, rz;
        if (j == 0) { rx = J[0]; ry = J[1]; rz = J[2]; }
        else {
            rx = J[3 * j + 0] - J[3 * p + 0];
            ry = J[3 * j + 1] - J[3 * p + 1];
            rz = J[3 * j + 2] - J[3 * p + 2];
        }

        if (j == 0) {
#pragma unroll
            for (int q = 0; q < 9; q++) cR[0][q] = R[q];
            cT[0][0] = rx; cT[0][1] = ry; cT[0][2] = rz;
        } else {
#pragma unroll
            for (int r = 0; r < 3; r++) {
#pragma unroll
                for (int cc = 0; cc < 3; cc++) {
                    cR[j][r * 3 + cc] = cR[p][r * 3 + 0] * R[0 + cc]
                                      + cR[p][r * 3 + 1] * R[3 + cc]
                                      + cR[p][r * 3 + 2] * R[6 + cc];
                }
                cT[j][r] = cR[p][r * 3 + 0] * rx + cR[p][r * 3 + 1] * ry
                         + cR[p][r * 3 + 2] * rz + cT[p][r];
            }
        }
        // Stage result in place (indices 3j..3j+2 already consumed this iter;
        // later iterations only read higher pose indices of this thread's row).
        Ps[tid][3 * j + 0] = cT[j][0] + tx;
        Ps[tid][3 * j + 1] = cT[j][1] + ty;
        Ps[tid][3 * j + 2] = cT[j][2] + tz;
    }
    __syncthreads();

    float* odst = out + (size_t)b0 * 72;
    for (int idx = tid; idx < 128 * 72; idx += 128) odst[idx] = Ps[idx / 72][idx % 72];
}

// ---------------------------------------------------------------------------
extern "C" void kernel_launch(void* const* d_in, const int* in_sizes, int n_in,
                              void* d_out, int out_size) {
    const float* pose  = (const float*)d_in[0];
    const float* trans = (const float*)d_in[1];
    const float* betas = (const float*)d_in[2];
    const float* vt    = (const float*)d_in[3];
    const float* sd    = (const float*)d_in[4];
    const float* jr    = (const float*)d_in[5];
    // d_in[6] = parents (int64) — SMPL kinematic tree, hardcoded above.
    float* out = (float*)d_out;

    kA <<<NBLK_A, 256>>>(vt, sd, jr);
    kA2<<<4, 256>>>();
    kB <<<32, 128>>>(pose, trans, betas, out);
}

// round 2
// speedup vs baseline: 1.1704x; 1.1704x over previous
#include <cuda_runtime.h>
#include <cuda_bf16.h>
#include <cstdint>

// ---------------------------------------------------------------------------
// SMPL joint regression. Batch-independent contraction of the vertex dim:
//   Jbase[j,k] = sum_i Jreg[j,i]*vt[i,k];  JS[j,k,l] = sum_i Jreg[j,i]*sd[i,k,l]
// then per batch: J = Jbase + JS.beta, Rodrigues, FK chain, +trans.
// Round-2 change: 4-8x more CTAs per kernel (latency/occupancy fix).
// ---------------------------------------------------------------------------

#define NUM_VERTS 6890
#define VB 32
#define NBLK_A 216           // ceil(6890/32)
#define NBASIS 792           // 24 joints * 33 cols (3 vt + 30 sd)

// transposed partials: coalesced reads in kA2
__device__ float g_part[NBASIS][NBLK_A];
__device__ float g_final[NBASIS];   // [0..71]=Jbase(j*3+k), [72+l*72+j*3+k]=JS

// ---------------- Kernel A: per-32-vert-chunk partial basis ------------------
__global__ void __launch_bounds__(256) kA(const float* __restrict__ vt,
                                          const float* __restrict__ sd,
                                          const float* __restrict__ jr) {
    __shared__ float Xs[VB][33];      // col 0..2 = v_template, 3..32 = shapedirs
    __shared__ float Jr[24][VB];
    const int i0 = blockIdx.x * VB;
    const int tid = threadIdx.x;

    // loads: 32*30 + 32*3 + 24*32 = 1824 floats over 256 threads, coalesced
    for (int idx = tid; idx < VB * 30; idx += 256) {
        int i = idx / 30, c = idx % 30;
        float v = 0.f;
        if (i0 + i < NUM_VERTS) v = sd[(size_t)i0 * 30 + idx];
        Xs[i][3 + c] = v;
    }
    if (tid < VB * 3) {
        int i = tid / 3, k = tid % 3;
        float v = 0.f;
        if (i0 + i < NUM_VERTS) v = vt[(size_t)(i0 + i) * 3 + k];
        Xs[i][k] = v;
    }
    for (int idx = tid; idx < 24 * VB; idx += 256) {
        int j = idx >> 5, i = idx & (VB - 1);
        float v = 0.f;
        if (i0 + i < NUM_VERTS) v = jr[j * NUM_VERTS + i0 + i];
        Jr[j][i] = v;
    }
    __syncthreads();

    const int w = tid >> 5, l = tid & 31;
    const int j0 = w, j1 = w + 8, j2 = w + 16;
    float a0 = 0.f, a1 = 0.f, a2 = 0.f;   // column l
    float b0 = 0.f, b1 = 0.f, b2 = 0.f;   // column 32 (lane 0 stores)
#pragma unroll
    for (int i = 0; i < VB; i++) {
        float r0 = Jr[j0][i], r1 = Jr[j1][i], r2 = Jr[j2][i];
        float x  = Xs[i][l];
        float xb = Xs[i][32];
        a0 += r0 * x;  a1 += r1 * x;  a2 += r2 * x;
        b0 += r0 * xb; b1 += r1 * xb; b2 += r2 * xb;
    }
    const int bx = blockIdx.x;
    g_part[j0 * 33 + l][bx] = a0;
    g_part[j1 * 33 + l][bx] = a1;
    g_part[j2 * 33 + l][bx] = a2;
    if (l == 0) {
        g_part[j0 * 33 + 32][bx] = b0;
        g_part[j1 * 33 + 32][bx] = b1;
        g_part[j2 * 33 + 32][bx] = b2;
    }
}

// ---------------- Kernel A2: one warp per output, coalesced ------------------
__global__ void __launch_bounds__(256) kA2() {
    const int w = (blockIdx.x * 256 + threadIdx.x) >> 5;  // global warp id
    const int l = threadIdx.x & 31;
    if (w >= NBASIS) return;
    float s = 0.f;
#pragma unroll
    for (int p = l; p < NBLK_A; p += 32) s += g_part[w][p];
#pragma unroll
    for (int off = 16; off > 0; off >>= 1)
        s += __shfl_down_sync(0xffffffffu, s, off);
    if (l == 0) {
        int j = w / 33, c = w % 33;
        int v;
        if (c < 3) v = j * 3 + c;
        else {
            int k = (c - 3) / 10, lb = (c - 3) % 10;
            v = 72 + lb * 72 + j * 3 + k;
        }
        g_final[v] = s;
    }
}

// ---------------- Kernel B: per-batch Rodrigues + FK (32 thr/blk) ------------
__global__ void __launch_bounds__(32) kB(const float* __restrict__ pose,
                                         const float* __restrict__ trans,
                                         const float* __restrict__ betas,
                                         float* __restrict__ out) {
    __shared__ float Jb[NBASIS];
    __shared__ float Ps[32][73];   // 73 odd & coprime with 32 -> conflict-free
    __shared__ float Bs[32][11];
    __shared__ float Ts[32][3];
    const int tid = threadIdx.x;
    const int b0 = blockIdx.x * 32;

    for (int v = tid; v < NBASIS; v += 32) Jb[v] = g_final[v];
    {
        const float* psrc = pose + (size_t)b0 * 72;
        for (int idx = tid; idx < 32 * 72; idx += 32) Ps[idx / 72][idx % 72] = psrc[idx];
        const float* bsrc = betas + (size_t)b0 * 10;
        for (int idx = tid; idx < 32 * 10; idx += 32) Bs[idx / 10][idx % 10] = bsrc[idx];
        const float* tsrc = trans + (size_t)b0 * 3;
        if (tid < 32 * 3 - 64) {}
        for (int idx = tid; idx < 32 * 3; idx += 32) Ts[idx / 3][idx % 3] = tsrc[idx];
    }
    __syncthreads();

    // J = Jbase + JS . beta
    float bet[10];
#pragma unroll
    for (int l = 0; l < 10; l++) bet[l] = Bs[tid][l];
    float J[72];
#pragma unroll
    for (int v = 0; v < 72; v++) J[v] = Jb[v];
#pragma unroll
    for (int l = 0; l < 10; l++) {
#pragma unroll
        for (int v = 0; v < 72; v++) J[v] += bet[l] * Jb[72 + l * 72 + v];
    }
    const float tx = Ts[tid][0], ty = Ts[tid][1], tz = Ts[tid][2];

    const int PAR[24] = {-1, 0, 0, 0, 1, 2, 3, 4, 5, 6, 7, 8,
                          9, 9, 9, 12, 13, 14, 16, 17, 18, 19, 20, 21};

    float cR[24][9], cT[24][3];
#pragma unroll
    for (int j = 0; j < 24; j++) {
        // --- Rodrigues (matches reference: angle = ||v + eps||) ---
        float vx = Ps[tid][3 * j + 0];
        float vy = Ps[tid][3 * j + 1];
        float vz = Ps[tid][3 * j + 2];
        float ax = vx + 1e-8f, ay = vy + 1e-8f, az = vz + 1e-8f;
        float n2 = ax * ax + ay * ay + az * az;
        float inv = rsqrtf(n2);
        float ang = n2 * inv;
        float x = vx * inv, y = vy * inv, z = vz * inv;
        float s, c;
        __sincosf(ang, &s, &c);
        float t1 = 1.f - c;
        float R[9];
        R[0] = 1.f - t1 * (y * y + z * z);
        R[1] = -s * z + t1 * x * y;
        R[2] =  s * y + t1 * x * z;
        R[3] =  s * z + t1 * x * y;
        R[4] = 1.f - t1 * (x * x + z * z);
        R[5] = -s * x + t1 * y * z;
        R[6] = -s * y + t1 * x * z;
        R[7] =  s * x + t1 * y * z;
        R[8] = 1.f - t1 * (x * x + y * y);

        int p = PAR[j];
        float rx, ry, rz;
        if (j == 0) { rx = J[0]; ry = J[1]; rz = J[2]; }
        else {
            rx = J[3 * j + 0] - J[3 * p + 0];
            ry = J[3 * j + 1] - J[3 * p + 1];
            rz = J[3 * j + 2] - J[3 * p + 2];
        }

        if (j == 0) {
#pragma unroll
            for (int q = 0; q < 9; q++) cR[0][q] = R[q];
            cT[0][0] = rx; cT[0][1] = ry; cT[0][2] = rz;
        } else {
#pragma unroll
            for (int r = 0; r < 3; r++) {
#pragma unroll
                for (int cc = 0; cc < 3; cc++) {
                    cR[j][r * 3 + cc] = cR[p][r * 3 + 0] * R[0 + cc]
                                      + cR[p][r * 3 + 1] * R[3 + cc]
                                      + cR[p][r * 3 + 2] * R[6 + cc];
                }
                cT[j][r] = cR[p][r * 3 + 0] * rx + cR[p][r * 3 + 1] * ry
                         + cR[p][r * 3 + 2] * rz + cT[p][r];
            }
        }
        // stage result in place (this iter already consumed pose[3j..3j+2])
        Ps[tid][3 * j + 0] = cT[j][0] + tx;
        Ps[tid][3 * j + 1] = cT[j][1] + ty;
        Ps[tid][3 * j + 2] = cT[j][2] + tz;
    }
    __syncthreads();

    float* odst = out + (size_t)b0 * 72;
    for (int idx = tid; idx < 32 * 72; idx += 32) odst[idx] = Ps[idx / 72][idx % 72];
}

// ---------------------------------------------------------------------------
extern "C" void kernel_launch(void* const* d_in, const int* in_sizes, int n_in,
                              void* d_out, int out_size) {
    const float* pose  = (const float*)d_in[0];
    const float* trans = (const float*)d_in[1];
    const float* betas = (const float*)d_in[2];
    const float* vt    = (const float*)d_in[3];
    const float* sd    = (const float*)d_in[4];
    const float* jr    = (const float*)d_in[5];
    // d_in[6] = parents (int64) — SMPL tree hardcoded above.
    float* out = (float*)d_out;

    kA <<<NBLK_A, 256>>>(vt, sd, jr);
    kA2<<<(NBASIS * 32 + 255) / 256, 256>>>();   // 99 blocks, 1 warp/output
    kB <<<4096 / 32, 32>>>(pose, trans, betas, out);
}